// round 9
// baseline (speedup 1.0000x reference)
#include <cuda_runtime.h>
#include <cuda_bf16.h>
#include <math.h>

#define BATCH   256
#define NPTS    8192
#define THREADS 512
#define SLICES  4                         // blocks per batch
#define NCH     ((NPTS * 3) / 12)         // 2048 chunks of 4 points per batch
#define CPB     (NCH / SLICES)            // 512 chunks per block (1 per thread)
#define GRID    (BATCH * SLICES)          // 1024 blocks
#define CLAMP_V 10.0f

// Scratch (no allocations allowed -> __device__ globals, zero-initialized)
__device__ float d_psums[GRID * 15];      // per-slice 15-term partials
__device__ int   d_bcount[BATCH];         // per-batch arrival counters
__device__ float d_RT[BATCH * 12];        // per batch: R row-major [9], t [3]
__device__ float d_partial[GRID];         // per-slice clamped-distance sums
__device__ int   d_count;                 // global arrival counter

__device__ __forceinline__ float warpSum(float v) {
#pragma unroll
    for (int o = 16; o; o >>= 1) v += __shfl_down_sync(0xffffffffu, v, o);
    return v;
}

// ---------------------------------------------------------------------------
// fp32 Kabsch solve from the 15 reduced sums (single thread).
// H = M - sumA sumB^T / N ; Jacobi eig of K = H^T H -> V, lam ; u_k = H v_k/sig
// R = sum_k s_k v_k u_k^T (sign flip on SMALLEST sigma iff det(H) < 0)
// == V diag(1,1,s) U^T as in the reference. t = cB - R cA.
// ---------------------------------------------------------------------------
__device__ void kabsch_solve(const float* __restrict__ s, float* __restrict__ rt) {
    const float invN = 1.0f / (float)NPTS;
    float sA[3] = {s[0], s[1], s[2]};
    float sB[3] = {s[3], s[4], s[5]};
    float H[3][3];
#pragma unroll
    for (int i = 0; i < 3; i++)
#pragma unroll
        for (int j = 0; j < 3; j++)
            H[i][j] = s[6 + i * 3 + j] - sA[i] * sB[j] * invN;

    float K[3][3];
#pragma unroll
    for (int i = 0; i < 3; i++)
#pragma unroll
        for (int j = 0; j < 3; j++)
            K[i][j] = H[0][i]*H[0][j] + H[1][i]*H[1][j] + H[2][i]*H[2][j];

    float V[3][3] = {{1,0,0},{0,1,0},{0,0,1}};
    const int PP[3] = {0, 0, 1};
    const int QQ[3] = {1, 2, 2};
    for (int sweep = 0; sweep < 8; sweep++) {
#pragma unroll
        for (int pair = 0; pair < 3; pair++) {
            const int p = PP[pair], q = QQ[pair];
            float apq = K[p][q];
            if (fabsf(apq) <= 1e-10f * (fabsf(K[p][p]) + fabsf(K[q][q]))) continue;
            float theta = (K[q][q] - K[p][p]) / (2.0f * apq);
            float t = (theta >= 0.0f) ? 1.0f / (theta + sqrtf(1.0f + theta * theta))
                                      : 1.0f / (theta - sqrtf(1.0f + theta * theta));
            float c = rsqrtf(1.0f + t * t);
            float sn = t * c;
#pragma unroll
            for (int k = 0; k < 3; k++) {
                float kp = K[k][p], kq = K[k][q];
                K[k][p] = c * kp - sn * kq;
                K[k][q] = sn * kp + c * kq;
            }
#pragma unroll
            for (int k = 0; k < 3; k++) {
                float pk = K[p][k], qk = K[q][k];
                K[p][k] = c * pk - sn * qk;
                K[q][k] = sn * pk + c * qk;
            }
#pragma unroll
            for (int k = 0; k < 3; k++) {
                float vp_ = V[k][p], vq_ = V[k][q];
                V[k][p] = c * vp_ - sn * vq_;
                V[k][q] = sn * vp_ + c * vq_;
            }
        }
    }

    float lam[3] = {K[0][0], K[1][1], K[2][2]};
    int imin = 0;
    if (lam[1] < lam[imin]) imin = 1;
    if (lam[2] < lam[imin]) imin = 2;

    float detH = H[0][0]*(H[1][1]*H[2][2] - H[1][2]*H[2][1])
               - H[0][1]*(H[1][0]*H[2][2] - H[1][2]*H[2][0])
               + H[0][2]*(H[1][0]*H[2][1] - H[1][1]*H[2][0]);

    float R[3][3] = {{0,0,0},{0,0,0},{0,0,0}};
#pragma unroll
    for (int k = 0; k < 3; k++) {
        float v0 = V[0][k], v1 = V[1][k], v2 = V[2][k];
        float hv0 = H[0][0]*v0 + H[0][1]*v1 + H[0][2]*v2;
        float hv1 = H[1][0]*v0 + H[1][1]*v1 + H[1][2]*v2;
        float hv2 = H[2][0]*v0 + H[2][1]*v1 + H[2][2]*v2;
        float coef = rsqrtf(fmaxf(lam[k], 1e-30f));
        if (k == imin && detH < 0.0f) coef = -coef;
        R[0][0] += coef * v0 * hv0; R[0][1] += coef * v0 * hv1; R[0][2] += coef * v0 * hv2;
        R[1][0] += coef * v1 * hv0; R[1][1] += coef * v1 * hv1; R[1][2] += coef * v1 * hv2;
        R[2][0] += coef * v2 * hv0; R[2][1] += coef * v2 * hv1; R[2][2] += coef * v2 * hv2;
    }

    float cA0 = sA[0]*invN, cA1 = sA[1]*invN, cA2 = sA[2]*invN;
    float cB0 = sB[0]*invN, cB1 = sB[1]*invN, cB2 = sB[2]*invN;

#pragma unroll
    for (int i = 0; i < 3; i++)
#pragma unroll
        for (int j = 0; j < 3; j++)
            rt[i * 3 + j] = R[i][j];
    rt[9]  = cB0 - (R[0][0]*cA0 + R[0][1]*cA1 + R[0][2]*cA2);
    rt[10] = cB1 - (R[1][0]*cA0 + R[1][1]*cA1 + R[1][2]*cA2);
    rt[11] = cB2 - (R[2][0]*cA0 + R[2][1]*cA1 + R[2][2]*cA2);
}

// ---------------------------------------------------------------------------
// Kernel 1: covariance partials (4 blocks per batch, 1 chunk of 4 pts/thread),
// per-batch last-block combines 4 slice partials in fixed order + Kabsch solve.
// ---------------------------------------------------------------------------
__global__ __launch_bounds__(THREADS) void k1_cov(const float* __restrict__ pred,
                                                  const float* __restrict__ truep) {
    const int b = blockIdx.x >> 2;
    const int slice = blockIdx.x & 3;
    const int c = slice * CPB + threadIdx.x;
    const float4* vp = reinterpret_cast<const float4*>(pred  + (size_t)b * NPTS * 3 + c * 12);
    const float4* vq = reinterpret_cast<const float4*>(truep + (size_t)b * NPTS * 3 + c * 12);

    float4 a0 = vp[0], a1 = vp[1], a2 = vp[2];
    float4 b0 = vq[0], b1 = vq[1], b2 = vq[2];
    float px[4] = {a0.x, a0.w, a1.z, a2.y};
    float py[4] = {a0.y, a1.x, a1.w, a2.z};
    float pz[4] = {a0.z, a1.y, a2.x, a2.w};
    float qx[4] = {b0.x, b0.w, b1.z, b2.y};
    float qy[4] = {b0.y, b1.x, b1.w, b2.z};
    float qz[4] = {b0.z, b1.y, b2.x, b2.w};

    float v15[15];
#pragma unroll
    for (int i = 0; i < 15; i++) v15[i] = 0.f;
#pragma unroll
    for (int i = 0; i < 4; i++) {
        v15[0] += px[i]; v15[1] += py[i]; v15[2] += pz[i];
        v15[3] += qx[i]; v15[4] += qy[i]; v15[5] += qz[i];
        v15[6]  += px[i]*qx[i]; v15[7]  += px[i]*qy[i]; v15[8]  += px[i]*qz[i];
        v15[9]  += py[i]*qx[i]; v15[10] += py[i]*qy[i]; v15[11] += py[i]*qz[i];
        v15[12] += pz[i]*qx[i]; v15[13] += pz[i]*qy[i]; v15[14] += pz[i]*qz[i];
    }

    __shared__ float ws[16][15];
    __shared__ float sh15[15];
    __shared__ bool  amLast;
    const int lane = threadIdx.x & 31, w = threadIdx.x >> 5;
#pragma unroll
    for (int q = 0; q < 15; q++) {
        float r = warpSum(v15[q]);
        if (lane == 0) ws[w][q] = r;
    }
    __syncthreads();
    if (threadIdx.x < 15) {
        float tot = 0.f;
#pragma unroll
        for (int i = 0; i < 16; i++) tot += ws[i][threadIdx.x];
        d_psums[blockIdx.x * 15 + threadIdx.x] = tot;
    }
    __syncthreads();
    if (threadIdx.x == 0) {
        __threadfence();
        int prev = atomicAdd(&d_bcount[b], 1);
        amLast = (prev == SLICES - 1);
    }
    __syncthreads();

    if (amLast) {
        __threadfence();
        if (threadIdx.x < 15) {
            float tot = 0.f;
#pragma unroll
            for (int s = 0; s < SLICES; s++)           // fixed order -> deterministic
                tot += d_psums[(b * SLICES + s) * 15 + threadIdx.x];
            sh15[threadIdx.x] = tot;
        }
        __syncthreads();
        if (threadIdx.x == 0) {
            kabsch_solve(sh15, &d_RT[b * 12]);
            d_bcount[b] = 0;                            // reset for next replay
        }
    }
}

// ---------------------------------------------------------------------------
// Kernel 2: apply (R, t), clamped distances (4 blocks/batch, 1 chunk/thread),
// per-slice sums, global last-block fixed-order final mean.
// aligned_j = sum_i p_i * R[i][j] + t[j]   (pred @ R, as in reference)
// ---------------------------------------------------------------------------
__global__ __launch_bounds__(THREADS) void k3_dist(const float* __restrict__ pred,
                                                   const float* __restrict__ truep,
                                                   float* __restrict__ out) {
    const int b = blockIdx.x >> 2;
    const int slice = blockIdx.x & 3;
    __shared__ float sRT[12];
    if (threadIdx.x < 12) sRT[threadIdx.x] = d_RT[b * 12 + threadIdx.x];
    __syncthreads();
    const float R00=sRT[0], R01=sRT[1], R02=sRT[2],
                R10=sRT[3], R11=sRT[4], R12=sRT[5],
                R20=sRT[6], R21=sRT[7], R22=sRT[8],
                t0 =sRT[9], t1 =sRT[10], t2 =sRT[11];

    const int c = slice * CPB + threadIdx.x;
    const float4* vp = reinterpret_cast<const float4*>(pred  + (size_t)b * NPTS * 3 + c * 12);
    const float4* vq = reinterpret_cast<const float4*>(truep + (size_t)b * NPTS * 3 + c * 12);
    float4 a0 = vp[0], a1 = vp[1], a2 = vp[2];
    float4 b0 = vq[0], b1 = vq[1], b2 = vq[2];
    float px[4] = {a0.x, a0.w, a1.z, a2.y};
    float py[4] = {a0.y, a1.x, a1.w, a2.z};
    float pz[4] = {a0.z, a1.y, a2.x, a2.w};
    float qx[4] = {b0.x, b0.w, b1.z, b2.y};
    float qy[4] = {b0.y, b1.x, b1.w, b2.z};
    float qz[4] = {b0.z, b1.y, b2.x, b2.w};

    float acc = 0.f;
#pragma unroll
    for (int i = 0; i < 4; i++) {
        float dx = px[i]*R00 + py[i]*R10 + pz[i]*R20 + t0 - qx[i];
        float dy = px[i]*R01 + py[i]*R11 + pz[i]*R21 + t1 - qy[i];
        float dz = px[i]*R02 + py[i]*R12 + pz[i]*R22 + t2 - qz[i];
        float d = sqrtf(dx*dx + dy*dy + dz*dz);
        acc += fminf(d, CLAMP_V);
    }

    __shared__ float ws[16];
    __shared__ bool  amLast;
    const int lane = threadIdx.x & 31, w = threadIdx.x >> 5;
    float r = warpSum(acc);
    if (lane == 0) ws[w] = r;
    __syncthreads();
    if (threadIdx.x == 0) {
        float t = 0.f;
#pragma unroll
        for (int i = 0; i < 16; i++) t += ws[i];
        d_partial[blockIdx.x] = t;
        __threadfence();
        int prev = atomicAdd(&d_count, 1);
        amLast = (prev == GRID - 1);
    }
    __syncthreads();

    // Deterministic final reduce by the last-arriving block: fixed pairing +
    // fixed-order shuffle tree over d_partial[0..1023].
    if (amLast) {
        __threadfence();
        float v = d_partial[threadIdx.x] + d_partial[threadIdx.x + THREADS];
        __shared__ float fs[16];
        float rr = warpSum(v);
        if (lane == 0) fs[w] = rr;
        __syncthreads();
        if (threadIdx.x == 0) {
            float tot = 0.f;
#pragma unroll
            for (int i = 0; i < 16; i++) tot += fs[i];
            out[0] = tot / ((float)BATCH * (float)NPTS);
            d_count = 0;                                // reset for next replay
        }
    }
}

extern "C" void kernel_launch(void* const* d_in, const int* in_sizes, int n_in,
                              void* d_out, int out_size) {
    // Inputs in metadata order: pred_frames, true_frames, pred_pos, true_pos.
    // Select the two [B,N,3] arrays (size B*N*3) in order; frames stay untouched.
    const int POS_ELEMS = BATCH * NPTS * 3;
    const float* pred_pos = nullptr;
    const float* true_pos = nullptr;
    for (int i = 0; i < n_in; i++) {
        if (in_sizes[i] == POS_ELEMS) {
            if (!pred_pos)      pred_pos = (const float*)d_in[i];
            else if (!true_pos) true_pos = (const float*)d_in[i];
        }
    }
    if (!pred_pos || !true_pos) {
        pred_pos = (const float*)d_in[2];
        true_pos = (const float*)d_in[3];
    }

    k1_cov <<<GRID, THREADS>>>(pred_pos, true_pos);
    k3_dist<<<GRID, THREADS>>>(pred_pos, true_pos, (float*)d_out);
}

// round 10
// speedup vs baseline: 1.3394x; 1.3394x over previous
#include <cuda_runtime.h>
#include <cuda_bf16.h>
#include <math.h>

#define BATCH   256
#define NPTS    8192
#define THREADS 512
#define ITERS   4                          // chunks (4 points) per thread
#define NCHUNK  (NPTS / 4)                 // 2048 chunks per batch
#define SLOT    13                         // padded words per chunk in smem (conflict-free)
#define SMEM_WORDS (NCHUNK * SLOT)         // 26624 words = 104 KB pred cache
#define CLAMP_V 10.0f

// Scratch (no allocations allowed -> __device__ globals)
__device__ float d_partial[BATCH];         // per-batch clamped-distance sums
__device__ int   d_count;                  // last-block counter (reset each replay)

__device__ __forceinline__ float warpSum(float v) {
#pragma unroll
    for (int o = 16; o; o >>= 1) v += __shfl_down_sync(0xffffffffu, v, o);
    return v;
}

// ---------------------------------------------------------------------------
// fp32 Kabsch solve from the 15 reduced sums (single thread).
// H = M - sumA sumB^T / N ; Jacobi eig of K = H^T H -> V, lam ; u_k = H v_k/sig
// R = sum_k s_k v_k u_k^T (sign flip on SMALLEST sigma iff det(H) < 0)
// == V diag(1,1,s) U^T as in the reference. t = cB - R cA.
// ---------------------------------------------------------------------------
__device__ void kabsch_solve(const float* __restrict__ s, float* __restrict__ rt) {
    const float invN = 1.0f / (float)NPTS;
    float sA[3] = {s[0], s[1], s[2]};
    float sB[3] = {s[3], s[4], s[5]};
    float H[3][3];
#pragma unroll
    for (int i = 0; i < 3; i++)
#pragma unroll
        for (int j = 0; j < 3; j++)
            H[i][j] = s[6 + i * 3 + j] - sA[i] * sB[j] * invN;

    float K[3][3];
#pragma unroll
    for (int i = 0; i < 3; i++)
#pragma unroll
        for (int j = 0; j < 3; j++)
            K[i][j] = H[0][i]*H[0][j] + H[1][i]*H[1][j] + H[2][i]*H[2][j];

    float V[3][3] = {{1,0,0},{0,1,0},{0,0,1}};
    const int PP[3] = {0, 0, 1};
    const int QQ[3] = {1, 2, 2};
    for (int sweep = 0; sweep < 8; sweep++) {
#pragma unroll
        for (int pair = 0; pair < 3; pair++) {
            const int p = PP[pair], q = QQ[pair];
            float apq = K[p][q];
            if (fabsf(apq) <= 1e-10f * (fabsf(K[p][p]) + fabsf(K[q][q]))) continue;
            float theta = (K[q][q] - K[p][p]) / (2.0f * apq);
            float t = (theta >= 0.0f) ? 1.0f / (theta + sqrtf(1.0f + theta * theta))
                                      : 1.0f / (theta - sqrtf(1.0f + theta * theta));
            float c = rsqrtf(1.0f + t * t);
            float sn = t * c;
#pragma unroll
            for (int k = 0; k < 3; k++) {
                float kp = K[k][p], kq = K[k][q];
                K[k][p] = c * kp - sn * kq;
                K[k][q] = sn * kp + c * kq;
            }
#pragma unroll
            for (int k = 0; k < 3; k++) {
                float pk = K[p][k], qk = K[q][k];
                K[p][k] = c * pk - sn * qk;
                K[q][k] = sn * pk + c * qk;
            }
#pragma unroll
            for (int k = 0; k < 3; k++) {
                float vp_ = V[k][p], vq_ = V[k][q];
                V[k][p] = c * vp_ - sn * vq_;
                V[k][q] = sn * vp_ + c * vq_;
            }
        }
    }

    float lam[3] = {K[0][0], K[1][1], K[2][2]};
    int imin = 0;
    if (lam[1] < lam[imin]) imin = 1;
    if (lam[2] < lam[imin]) imin = 2;

    float detH = H[0][0]*(H[1][1]*H[2][2] - H[1][2]*H[2][1])
               - H[0][1]*(H[1][0]*H[2][2] - H[1][2]*H[2][0])
               + H[0][2]*(H[1][0]*H[2][1] - H[1][1]*H[2][0]);

    float R[3][3] = {{0,0,0},{0,0,0},{0,0,0}};
#pragma unroll
    for (int k = 0; k < 3; k++) {
        float v0 = V[0][k], v1 = V[1][k], v2 = V[2][k];
        float hv0 = H[0][0]*v0 + H[0][1]*v1 + H[0][2]*v2;
        float hv1 = H[1][0]*v0 + H[1][1]*v1 + H[1][2]*v2;
        float hv2 = H[2][0]*v0 + H[2][1]*v1 + H[2][2]*v2;
        float coef = rsqrtf(fmaxf(lam[k], 1e-30f));
        if (k == imin && detH < 0.0f) coef = -coef;
        R[0][0] += coef * v0 * hv0; R[0][1] += coef * v0 * hv1; R[0][2] += coef * v0 * hv2;
        R[1][0] += coef * v1 * hv0; R[1][1] += coef * v1 * hv1; R[1][2] += coef * v1 * hv2;
        R[2][0] += coef * v2 * hv0; R[2][1] += coef * v2 * hv1; R[2][2] += coef * v2 * hv2;
    }

    float cA0 = sA[0]*invN, cA1 = sA[1]*invN, cA2 = sA[2]*invN;
    float cB0 = sB[0]*invN, cB1 = sB[1]*invN, cB2 = sB[2]*invN;

#pragma unroll
    for (int i = 0; i < 3; i++)
#pragma unroll
        for (int j = 0; j < 3; j++)
            rt[i * 3 + j] = R[i][j];
    rt[9]  = cB0 - (R[0][0]*cA0 + R[0][1]*cA1 + R[0][2]*cA2);
    rt[10] = cB1 - (R[1][0]*cA0 + R[1][1]*cA1 + R[1][2]*cA2);
    rt[11] = cB2 - (R[2][0]*cA0 + R[2][1]*cA1 + R[2][2]*cA2);
}

// ---------------------------------------------------------------------------
// Fused kernel: one block per batch.
// Phase A: stream pred/true (float4), accumulate 15 covariance terms, cache
//          pred in smem (stride-13 scalar slots -> conflict-free LDS/STS).
// Solve:   thread 0 runs fp32 Kabsch, R,t stay in this block's shared memory.
// Phase B: re-read true (L2-warm), pred from smem, clamped distances, per-batch
//          sum, global last-block fixed-order mean.
// ---------------------------------------------------------------------------
__global__ __launch_bounds__(THREADS, 2)
void fused_fape(const float* __restrict__ pred, const float* __restrict__ truep,
                float* __restrict__ out) {
    extern __shared__ float sp[];          // SMEM_WORDS: pred cache
    __shared__ float ws[16][15];
    __shared__ float sh15[15];
    __shared__ float sRT[12];
    __shared__ float ws2[16];
    __shared__ bool  amLast;

    const int b = blockIdx.x;
    const float* pp = pred  + (size_t)b * NPTS * 3;
    const float* qq = truep + (size_t)b * NPTS * 3;
    const int lane = threadIdx.x & 31, w = threadIdx.x >> 5;

    // ---------- Phase A: covariance accumulation + pred -> smem ----------
    float v15[15];
#pragma unroll
    for (int i = 0; i < 15; i++) v15[i] = 0.f;

#pragma unroll
    for (int it = 0; it < ITERS; it++) {
        const int c = threadIdx.x + it * THREADS;           // chunk of 4 points
        const float4* vp = reinterpret_cast<const float4*>(pp + c * 12);
        const float4* vq = reinterpret_cast<const float4*>(qq + c * 12);
        float4 a0 = vp[0], a1 = vp[1], a2 = vp[2];
        float4 b0 = vq[0], b1 = vq[1], b2 = vq[2];

        // cache pred chunk in smem (12 words in a 13-word slot: conflict-free)
        float pw[12] = {a0.x, a0.y, a0.z, a0.w, a1.x, a1.y,
                        a1.z, a1.w, a2.x, a2.y, a2.z, a2.w};
        const int base = c * SLOT;
#pragma unroll
        for (int j = 0; j < 12; j++) sp[base + j] = pw[j];

        float px[4] = {a0.x, a0.w, a1.z, a2.y};
        float py[4] = {a0.y, a1.x, a1.w, a2.z};
        float pz[4] = {a0.z, a1.y, a2.x, a2.w};
        float qx[4] = {b0.x, b0.w, b1.z, b2.y};
        float qy[4] = {b0.y, b1.x, b1.w, b2.z};
        float qz[4] = {b0.z, b1.y, b2.x, b2.w};
#pragma unroll
        for (int i = 0; i < 4; i++) {
            v15[0] += px[i]; v15[1] += py[i]; v15[2] += pz[i];
            v15[3] += qx[i]; v15[4] += qy[i]; v15[5] += qz[i];
            v15[6]  += px[i]*qx[i]; v15[7]  += px[i]*qy[i]; v15[8]  += px[i]*qz[i];
            v15[9]  += py[i]*qx[i]; v15[10] += py[i]*qy[i]; v15[11] += py[i]*qz[i];
            v15[12] += pz[i]*qx[i]; v15[13] += pz[i]*qy[i]; v15[14] += pz[i]*qz[i];
        }
    }

#pragma unroll
    for (int q = 0; q < 15; q++) {
        float r = warpSum(v15[q]);
        if (lane == 0) ws[w][q] = r;
    }
    __syncthreads();
    if (threadIdx.x < 15) {
        float tot = 0.f;
#pragma unroll
        for (int i = 0; i < 16; i++) tot += ws[i][threadIdx.x];
        sh15[threadIdx.x] = tot;
    }
    __syncthreads();

    // ---------- Kabsch solve (thread 0) -> shared R,t ----------
    if (threadIdx.x == 0) kabsch_solve(sh15, sRT);
    __syncthreads();

    const float R00=sRT[0], R01=sRT[1], R02=sRT[2],
                R10=sRT[3], R11=sRT[4], R12=sRT[5],
                R20=sRT[6], R21=sRT[7], R22=sRT[8],
                t0 =sRT[9], t1 =sRT[10], t2 =sRT[11];

    // ---------- Phase B: distances (true from L2, pred from smem) ----------
    float acc = 0.f;
#pragma unroll
    for (int it = 0; it < ITERS; it++) {
        const int c = threadIdx.x + it * THREADS;
        const float4* vq = reinterpret_cast<const float4*>(qq + c * 12);
        float4 b0 = vq[0], b1 = vq[1], b2 = vq[2];
        const int base = c * SLOT;
        float pw[12];
#pragma unroll
        for (int j = 0; j < 12; j++) pw[j] = sp[base + j];

        float px[4] = {pw[0], pw[3], pw[6], pw[9]};
        float py[4] = {pw[1], pw[4], pw[7], pw[10]};
        float pz[4] = {pw[2], pw[5], pw[8], pw[11]};
        float qx[4] = {b0.x, b0.w, b1.z, b2.y};
        float qy[4] = {b0.y, b1.x, b1.w, b2.z};
        float qz[4] = {b0.z, b1.y, b2.x, b2.w};
#pragma unroll
        for (int i = 0; i < 4; i++) {
            float dx = px[i]*R00 + py[i]*R10 + pz[i]*R20 + t0 - qx[i];
            float dy = px[i]*R01 + py[i]*R11 + pz[i]*R21 + t1 - qy[i];
            float dz = px[i]*R02 + py[i]*R12 + pz[i]*R22 + t2 - qz[i];
            float d = sqrtf(dx*dx + dy*dy + dz*dz);
            acc += fminf(d, CLAMP_V);
        }
    }

    float r = warpSum(acc);
    if (lane == 0) ws2[w] = r;
    __syncthreads();
    if (threadIdx.x == 0) {
        float t = 0.f;
#pragma unroll
        for (int i = 0; i < 16; i++) t += ws2[i];
        d_partial[b] = t;
        __threadfence();
        int prev = atomicAdd(&d_count, 1);
        amLast = (prev == BATCH - 1);
    }
    __syncthreads();

    // Deterministic final reduce by the last-arriving block (fixed order).
    if (amLast) {
        __threadfence();
        float v = (threadIdx.x < BATCH) ? d_partial[threadIdx.x] : 0.f;
        float rr = warpSum(v);
        __shared__ float fs[16];
        if (lane == 0) fs[w] = rr;
        __syncthreads();
        if (threadIdx.x == 0) {
            float tot = 0.f;
#pragma unroll
            for (int i = 0; i < 8; i++) tot += fs[i];    // first 8 warps hold 256 values
            out[0] = tot / ((float)BATCH * (float)NPTS);
            d_count = 0;                                  // reset for next replay
        }
    }
}

extern "C" void kernel_launch(void* const* d_in, const int* in_sizes, int n_in,
                              void* d_out, int out_size) {
    // Inputs in metadata order: pred_frames, true_frames, pred_pos, true_pos.
    // Select the two [B,N,3] arrays (size B*N*3) in order; frames stay untouched.
    const int POS_ELEMS = BATCH * NPTS * 3;
    const float* pred_pos = nullptr;
    const float* true_pos = nullptr;
    for (int i = 0; i < n_in; i++) {
        if (in_sizes[i] == POS_ELEMS) {
            if (!pred_pos)      pred_pos = (const float*)d_in[i];
            else if (!true_pos) true_pos = (const float*)d_in[i];
        }
    }
    if (!pred_pos || !true_pos) {
        pred_pos = (const float*)d_in[2];
        true_pos = (const float*)d_in[3];
    }

    const int smem_bytes = SMEM_WORDS * 4;   // 106496 B dynamic
    cudaFuncSetAttribute(fused_fape, cudaFuncAttributeMaxDynamicSharedMemorySize,
                         smem_bytes);
    fused_fape<<<BATCH, THREADS, smem_bytes>>>(pred_pos, true_pos, (float*)d_out);
}

// round 11
// speedup vs baseline: 1.3431x; 1.0028x over previous
#include <cuda_runtime.h>
#include <cuda_bf16.h>
#include <math.h>

#define BATCH   256
#define NPTS    8192
#define THREADS 512
#define NCH     ((NPTS * 3) / 12)        // 2048 chunks of 4 points
#define ITERS   (NCH / THREADS)          // 4
#define CLAMP_V 10.0f

// Scratch (no allocations allowed -> __device__ globals)
__device__ float d_RT[BATCH * 12];       // per batch: R row-major [9], t [3]
__device__ float d_partial[BATCH];       // per-batch clamped-distance sums
__device__ int   d_count;                // last-block counter (reset each replay)

__device__ __forceinline__ float warpSum(float v) {
#pragma unroll
    for (int o = 16; o; o >>= 1) v += __shfl_down_sync(0xffffffffu, v, o);
    return v;
}

// ---------------------------------------------------------------------------
// fp32 Kabsch solve from the 15 reduced sums (single thread).
// H = M - sumA sumB^T / N ; Jacobi eig of K = H^T H -> V, lam ; u_k = H v_k/sig
// R = sum_k s_k v_k u_k^T (sign flip on SMALLEST sigma iff det(H) < 0)
// == V diag(1,1,s) U^T as in the reference. t = cB - R cA.
// 5 sweeps: Jacobi is quadratically convergent; 3x3 random-Gaussian H is
// well-conditioned, off-diagonals are ~1e-12 by sweep 4.
// ---------------------------------------------------------------------------
__device__ void kabsch_solve(const float* __restrict__ s, float* __restrict__ rt) {
    const float invN = 1.0f / (float)NPTS;
    float sA[3] = {s[0], s[1], s[2]};
    float sB[3] = {s[3], s[4], s[5]};
    float H[3][3];
#pragma unroll
    for (int i = 0; i < 3; i++)
#pragma unroll
        for (int j = 0; j < 3; j++)
            H[i][j] = s[6 + i * 3 + j] - sA[i] * sB[j] * invN;

    float K[3][3];
#pragma unroll
    for (int i = 0; i < 3; i++)
#pragma unroll
        for (int j = 0; j < 3; j++)
            K[i][j] = H[0][i]*H[0][j] + H[1][i]*H[1][j] + H[2][i]*H[2][j];

    float V[3][3] = {{1,0,0},{0,1,0},{0,0,1}};
    const int PP[3] = {0, 0, 1};
    const int QQ[3] = {1, 2, 2};
    for (int sweep = 0; sweep < 5; sweep++) {
#pragma unroll
        for (int pair = 0; pair < 3; pair++) {
            const int p = PP[pair], q = QQ[pair];
            float apq = K[p][q];
            if (fabsf(apq) <= 1e-10f * (fabsf(K[p][p]) + fabsf(K[q][q]))) continue;
            float theta = (K[q][q] - K[p][p]) / (2.0f * apq);
            float t = (theta >= 0.0f) ? 1.0f / (theta + sqrtf(1.0f + theta * theta))
                                      : 1.0f / (theta - sqrtf(1.0f + theta * theta));
            float c = rsqrtf(1.0f + t * t);
            float sn = t * c;
#pragma unroll
            for (int k = 0; k < 3; k++) {
                float kp = K[k][p], kq = K[k][q];
                K[k][p] = c * kp - sn * kq;
                K[k][q] = sn * kp + c * kq;
            }
#pragma unroll
            for (int k = 0; k < 3; k++) {
                float pk = K[p][k], qk = K[q][k];
                K[p][k] = c * pk - sn * qk;
                K[q][k] = sn * pk + c * qk;
            }
#pragma unroll
            for (int k = 0; k < 3; k++) {
                float vp_ = V[k][p], vq_ = V[k][q];
                V[k][p] = c * vp_ - sn * vq_;
                V[k][q] = sn * vp_ + c * vq_;
            }
        }
    }

    float lam[3] = {K[0][0], K[1][1], K[2][2]};
    int imin = 0;
    if (lam[1] < lam[imin]) imin = 1;
    if (lam[2] < lam[imin]) imin = 2;

    float detH = H[0][0]*(H[1][1]*H[2][2] - H[1][2]*H[2][1])
               - H[0][1]*(H[1][0]*H[2][2] - H[1][2]*H[2][0])
               + H[0][2]*(H[1][0]*H[2][1] - H[1][1]*H[2][0]);

    float R[3][3] = {{0,0,0},{0,0,0},{0,0,0}};
#pragma unroll
    for (int k = 0; k < 3; k++) {
        float v0 = V[0][k], v1 = V[1][k], v2 = V[2][k];
        float hv0 = H[0][0]*v0 + H[0][1]*v1 + H[0][2]*v2;
        float hv1 = H[1][0]*v0 + H[1][1]*v1 + H[1][2]*v2;
        float hv2 = H[2][0]*v0 + H[2][1]*v1 + H[2][2]*v2;
        float coef = rsqrtf(fmaxf(lam[k], 1e-30f));
        if (k == imin && detH < 0.0f) coef = -coef;
        R[0][0] += coef * v0 * hv0; R[0][1] += coef * v0 * hv1; R[0][2] += coef * v0 * hv2;
        R[1][0] += coef * v1 * hv0; R[1][1] += coef * v1 * hv1; R[1][2] += coef * v1 * hv2;
        R[2][0] += coef * v2 * hv0; R[2][1] += coef * v2 * hv1; R[2][2] += coef * v2 * hv2;
    }

    float cA0 = sA[0]*invN, cA1 = sA[1]*invN, cA2 = sA[2]*invN;
    float cB0 = sB[0]*invN, cB1 = sB[1]*invN, cB2 = sB[2]*invN;

#pragma unroll
    for (int i = 0; i < 3; i++)
#pragma unroll
        for (int j = 0; j < 3; j++)
            rt[i * 3 + j] = R[i][j];
    rt[9]  = cB0 - (R[0][0]*cA0 + R[0][1]*cA1 + R[0][2]*cA2);
    rt[10] = cB1 - (R[1][0]*cA0 + R[1][1]*cA1 + R[1][2]*cA2);
    rt[11] = cB2 - (R[2][0]*cA0 + R[2][1]*cA1 + R[2][2]*cA2);
}

// ---------------------------------------------------------------------------
// Kernel 1: per-batch reduction of 15 covariance terms + fused Kabsch solve.
// One block per batch, 512 threads, front-batched float4 loads. Triggers PDL
// completion as soon as d_RT is globally visible.
// ---------------------------------------------------------------------------
__global__ __launch_bounds__(THREADS) void k1_cov(const float* __restrict__ pred,
                                                  const float* __restrict__ truep) {
    const int b = blockIdx.x;
    const float* pp = pred  + (size_t)b * NPTS * 3;
    const float* qq = truep + (size_t)b * NPTS * 3;

    float sA0=0.f,sA1=0.f,sA2=0.f,sB0=0.f,sB1=0.f,sB2=0.f;
    float m00=0.f,m01=0.f,m02=0.f,m10=0.f,m11=0.f,m12=0.f,m20=0.f,m21=0.f,m22=0.f;

    // Front-batch all loads: 4 fully-unrolled iterations x 6 float4 = 24 LDG.128
    float4 A[ITERS][3], Bv[ITERS][3];
#pragma unroll
    for (int it = 0; it < ITERS; it++) {
        const int c = threadIdx.x + it * THREADS;
        const float4* vp = reinterpret_cast<const float4*>(pp + c * 12);
        const float4* vq = reinterpret_cast<const float4*>(qq + c * 12);
        A[it][0] = vp[0]; A[it][1] = vp[1]; A[it][2] = vp[2];
        Bv[it][0] = vq[0]; Bv[it][1] = vq[1]; Bv[it][2] = vq[2];
    }
#pragma unroll
    for (int it = 0; it < ITERS; it++) {
        float4 a0 = A[it][0], a1 = A[it][1], a2 = A[it][2];
        float4 b0 = Bv[it][0], b1 = Bv[it][1], b2 = Bv[it][2];
        float px[4] = {a0.x, a0.w, a1.z, a2.y};
        float py[4] = {a0.y, a1.x, a1.w, a2.z};
        float pz[4] = {a0.z, a1.y, a2.x, a2.w};
        float qx[4] = {b0.x, b0.w, b1.z, b2.y};
        float qy[4] = {b0.y, b1.x, b1.w, b2.z};
        float qz[4] = {b0.z, b1.y, b2.x, b2.w};
#pragma unroll
        for (int i = 0; i < 4; i++) {
            sA0 += px[i]; sA1 += py[i]; sA2 += pz[i];
            sB0 += qx[i]; sB1 += qy[i]; sB2 += qz[i];
            m00 += px[i]*qx[i]; m01 += px[i]*qy[i]; m02 += px[i]*qz[i];
            m10 += py[i]*qx[i]; m11 += py[i]*qy[i]; m12 += py[i]*qz[i];
            m20 += pz[i]*qx[i]; m21 += pz[i]*qy[i]; m22 += pz[i]*qz[i];
        }
    }

    __shared__ float ws[16][15];
    __shared__ float sh15[15];
    float vals[15] = {sA0,sA1,sA2,sB0,sB1,sB2,m00,m01,m02,m10,m11,m12,m20,m21,m22};
    const int lane = threadIdx.x & 31, w = threadIdx.x >> 5;
#pragma unroll
    for (int q = 0; q < 15; q++) {
        float r = warpSum(vals[q]);
        if (lane == 0) ws[w][q] = r;
    }
    __syncthreads();
    if (threadIdx.x < 15) {
        float tot = 0.f;
#pragma unroll
        for (int i = 0; i < 16; i++) tot += ws[i][threadIdx.x];
        sh15[threadIdx.x] = tot;
    }
    __syncthreads();

    if (threadIdx.x == 0) {
        kabsch_solve(sh15, &d_RT[b * 12]);
        __threadfence();                    // d_RT visible before trigger
    }
    __syncthreads();
    cudaTriggerProgrammaticLaunchCompletion();   // let k3 proceed ASAP
}

// ---------------------------------------------------------------------------
// Kernel 2: apply (R, t), clamped distances, per-batch sum, fused final mean.
// Launched with PDL: issues its own p/q loads BEFORE cudaGridDependency-
// Synchronize so the first DRAM round-trip overlaps k1's tail.
// aligned_j = sum_i p_i * R[i][j] + t[j]   (pred @ R, as in reference)
// ---------------------------------------------------------------------------
__global__ __launch_bounds__(THREADS) void k3_dist(const float* __restrict__ pred,
                                                   const float* __restrict__ truep,
                                                   float* __restrict__ out) {
    const int b = blockIdx.x;
    const float* pp = pred  + (size_t)b * NPTS * 3;
    const float* qq = truep + (size_t)b * NPTS * 3;

    // Prefetch all data BEFORE the dependency sync (inputs are read-only and
    // not written by k1, so this is safe) — overlaps DRAM latency with k1 tail.
    float4 A[ITERS][3], Bv[ITERS][3];
#pragma unroll
    for (int it = 0; it < ITERS; it++) {
        const int c = threadIdx.x + it * THREADS;
        const float4* vp = reinterpret_cast<const float4*>(pp + c * 12);
        const float4* vq = reinterpret_cast<const float4*>(qq + c * 12);
        A[it][0] = vp[0]; A[it][1] = vp[1]; A[it][2] = vp[2];
        Bv[it][0] = vq[0]; Bv[it][1] = vq[1]; Bv[it][2] = vq[2];
    }

    cudaGridDependencySynchronize();        // wait for k1's d_RT

    __shared__ float sRT[12];
    if (threadIdx.x < 12) sRT[threadIdx.x] = d_RT[b * 12 + threadIdx.x];
    __syncthreads();
    const float R00=sRT[0], R01=sRT[1], R02=sRT[2],
                R10=sRT[3], R11=sRT[4], R12=sRT[5],
                R20=sRT[6], R21=sRT[7], R22=sRT[8],
                t0 =sRT[9], t1 =sRT[10], t2 =sRT[11];

    float acc = 0.f;
#pragma unroll
    for (int it = 0; it < ITERS; it++) {
        float4 a0 = A[it][0], a1 = A[it][1], a2 = A[it][2];
        float4 b0 = Bv[it][0], b1 = Bv[it][1], b2 = Bv[it][2];
        float px[4] = {a0.x, a0.w, a1.z, a2.y};
        float py[4] = {a0.y, a1.x, a1.w, a2.z};
        float pz[4] = {a0.z, a1.y, a2.x, a2.w};
        float qx[4] = {b0.x, b0.w, b1.z, b2.y};
        float qy[4] = {b0.y, b1.x, b1.w, b2.z};
        float qz[4] = {b0.z, b1.y, b2.x, b2.w};
#pragma unroll
        for (int i = 0; i < 4; i++) {
            float dx = px[i]*R00 + py[i]*R10 + pz[i]*R20 + t0 - qx[i];
            float dy = px[i]*R01 + py[i]*R11 + pz[i]*R21 + t1 - qy[i];
            float dz = px[i]*R02 + py[i]*R12 + pz[i]*R22 + t2 - qz[i];
            float d = sqrtf(dx*dx + dy*dy + dz*dz);
            acc += fminf(d, CLAMP_V);
        }
    }

    __shared__ float ws[16];
    __shared__ bool  amLast;
    const int lane = threadIdx.x & 31, w = threadIdx.x >> 5;
    float r = warpSum(acc);
    if (lane == 0) ws[w] = r;
    __syncthreads();
    if (threadIdx.x == 0) {
        float t = 0.f;
#pragma unroll
        for (int i = 0; i < 16; i++) t += ws[i];
        d_partial[b] = t;
        __threadfence();
        int prev = atomicAdd(&d_count, 1);
        amLast = (prev == BATCH - 1);
    }
    __syncthreads();

    // Deterministic final reduce by the last-arriving block (fixed order).
    if (amLast) {
        __threadfence();
        float v = (threadIdx.x < BATCH) ? d_partial[threadIdx.x] : 0.f;
        __shared__ float fs[16];
        float rr = warpSum(v);
        if (lane == 0) fs[w] = rr;
        __syncthreads();
        if (threadIdx.x == 0) {
            float tot = 0.f;
#pragma unroll
            for (int i = 0; i < 8; i++) tot += fs[i];   // first 8 warps hold 256 values
            out[0] = tot / ((float)BATCH * (float)NPTS);
            d_count = 0;                                // reset for next replay
        }
    }
}

extern "C" void kernel_launch(void* const* d_in, const int* in_sizes, int n_in,
                              void* d_out, int out_size) {
    // Inputs in metadata order: pred_frames, true_frames, pred_pos, true_pos.
    // Select the two [B,N,3] arrays (size B*N*3) in order; frames stay untouched.
    const int POS_ELEMS = BATCH * NPTS * 3;
    const float* pred_pos = nullptr;
    const float* true_pos = nullptr;
    for (int i = 0; i < n_in; i++) {
        if (in_sizes[i] == POS_ELEMS) {
            if (!pred_pos)      pred_pos = (const float*)d_in[i];
            else if (!true_pos) true_pos = (const float*)d_in[i];
        }
    }
    if (!pred_pos || !true_pos) {
        pred_pos = (const float*)d_in[2];
        true_pos = (const float*)d_in[3];
    }

    k1_cov<<<BATCH, THREADS>>>(pred_pos, true_pos);

    // k3 with programmatic dependent launch: overlaps its prologue/loads with
    // k1's epilogue; cudaGridDependencySynchronize() in-kernel provides the
    // ordering on d_RT.
    cudaLaunchConfig_t cfg = {};
    cfg.gridDim  = dim3(BATCH, 1, 1);
    cfg.blockDim = dim3(THREADS, 1, 1);
    cfg.dynamicSmemBytes = 0;
    cfg.stream = 0;
    cudaLaunchAttribute attr[1];
    attr[0].id = cudaLaunchAttributeProgrammaticStreamSerialization;
    attr[0].val.programmaticStreamSerializationAllowed = 1;
    cfg.attrs = attr;
    cfg.numAttrs = 1;
    cudaLaunchKernelEx(&cfg, k3_dist, pred_pos, true_pos, (float*)d_out);
}